// round 13
// baseline (speedup 1.0000x reference)
#include <cuda_runtime.h>
#include <stdint.h>
#include <math.h>

#define T_LEN 8192
#define NT 768
#define XS 36
#define SESTR 104

// float offsets in dynamic smem
#define OFF_X0  0                       // 77 x XS
#define OFF_X1  2772                    // 77 x XS
#define OFF_RB  5544                    // 76 x XS
#define OFF_GT  8280                    // 75 x XS
#define OFF_PB  10980                   // 64 x XS partial-sum scratch
#define OFF_WB  13284                   // 3 weight buffers
#define WBSZ    8192
#define WDO 0
#define WFO 2304
#define WGO 4608
#define WRO 6912
#define BSO 8064
#define SMEM_FLOATS (OFF_WB + 3*WBSZ)   // 37860 floats = 151440 B

typedef unsigned long long u64;

// per-layer split point c (rank0 owns [0,c), computes RB[0..c]; rank1 owns [c,W])
__device__ const int d_cArr[16] = {38,37,34,30,29,27,25,20,19,18,15,11,10,8,6,1};
// halo pushed by rank1 into rank0's Xw: positions [R0LO, R0HI]
__device__ const int d_R0LO[15] = {38,37,34,30,29,27,25,20,19,18,15,11,10, 8, 6};
__device__ const int d_R0HI[15] = {39,38,38,30,29,29,28,20,20,19,19,11,10,10, 9};
// halo pushed by rank0 into rank1's Xw: positions [R1LO, R1HI] (li=14: empty)
__device__ const int d_R1LO[15] = {37,34,30,29,27,25,20,19,18,15,11,10, 8, 6, 1};
__device__ const int d_R1HI[15] = {37,36,33,29,28,26,24,19,18,17,14,10, 9, 7, 0};

__device__ __forceinline__ u64 pack2(float lo, float hi) {
    u64 r; asm("mov.b64 %0,{%1,%2};" : "=l"(r) : "f"(lo), "f"(hi)); return r;
}
__device__ __forceinline__ u64 dup2(float x) { return pack2(x, x); }
__device__ __forceinline__ void fma2(u64& a, u64 w, u64 x) {
    asm("fma.rn.f32x2 %0,%1,%2,%0;" : "+l"(a) : "l"(w), "l"(x));
}
__device__ __forceinline__ u64 add2(u64 a, u64 b) {
    u64 r; asm("add.rn.f32x2 %0,%1,%2;" : "=l"(r) : "l"(a), "l"(b)); return r;
}
__device__ __forceinline__ float2 unpk(u64 a) {
    float2 f; asm("mov.b64 {%0,%1},%2;" : "=f"(f.x), "=f"(f.y) : "l"(a)); return f;
}
__device__ __forceinline__ float warp_sum(float v) {
    #pragma unroll
    for (int o = 16; o; o >>= 1) v += __shfl_xor_sync(0xffffffffu, v, o);
    return v;
}
__device__ __forceinline__ float fast_tanh(float x) {
    float e = __expf(-2.0f * x);
    return fmaf(2.0f, __frcp_rn(1.0f + e), -1.0f);
}
__device__ __forceinline__ float fast_sig(float x) {
    return __frcp_rn(1.0f + __expf(-x));
}
__device__ __forceinline__ float dot4(float4 a, float4 b) {
    return fmaf(a.x, b.x, fmaf(a.y, b.y, fmaf(a.z, b.z, a.w * b.w)));
}

__global__ void __launch_bounds__(NT, 1) __cluster_dims__(2, 1, 1)
wavenet_kernel(
    const int*   __restrict__ tokens,
    const float* __restrict__ emb,
    const float* __restrict__ init_w, const float* __restrict__ init_b,
    const float* __restrict__ dil_w,  const float* __restrict__ dil_b,
    const float* __restrict__ filt_w, const float* __restrict__ filt_b,
    const float* __restrict__ gate_w, const float* __restrict__ gate_b,
    const float* __restrict__ res_w,  const float* __restrict__ res_b,
    const float* __restrict__ skip_w, const float* __restrict__ skip_b,
    const float* __restrict__ end1_w, const float* __restrict__ end1_b,
    const float* __restrict__ end2_w, const float* __restrict__ end2_b,
    const float* __restrict__ fc1_w,  const float* __restrict__ fc1_b,
    const float* __restrict__ fc2_w,  const float* __restrict__ fc2_b,
    const float* __restrict__ fc3_w,  const float* __restrict__ fc3_b,
    const float* __restrict__ fc4_w,  const float* __restrict__ fc4_b,
    float* __restrict__ out)
{
    extern __shared__ float sm[];
    __shared__ int stok[77];

    float* X0 = sm + OFF_X0;
    float* X1 = sm + OFF_X1;
    float* RB = sm + OFF_RB;
    float* GT = sm + OFF_GT;
    float* PB = sm + OFF_PB;

    const int b    = blockIdx.x >> 1;
    int rank_;
    asm("mov.u32 %0, %%cluster_ctarank;" : "=r"(rank_));
    const int rank = rank_;
    const int peer = rank ^ 1;
    const int tid  = threadIdx.x;
    const int lane = tid & 31;
    const int warp = tid >> 5;
    const int cg   = warp & 7;
    const int pg   = (warp >> 3) & 1;
    const int cb   = cg * 4;
    const int s    = tid - 512;

    uint32_t smem_u32;
    asm("{ .reg .u64 t; cvta.to.shared.u64 t, %1; cvt.u32.u64 %0, t; }"
        : "=r"(smem_u32) : "l"(sm));

    auto stage = [&](int li, int bi) {
        float* Bf = sm + OFF_WB + bi * WBSZ;
        const float* gd = dil_w  + li * 2048;
        const float* gf = filt_w + li * 2048;
        const float* gg = gate_w + li * 2048;
        const float* gr = res_w  + li * 1024;
        #pragma unroll
        for (int k = 0; k < 8; k++) {
            int t = s + 256 * k;
            int c = t >> 6, rk = t & 63;
            int o = rk * XS + c;
            Bf[WDO + o] = __ldg(gd + t);
            Bf[WFO + o] = __ldg(gf + t);
            Bf[WGO + o] = __ldg(gg + t);
        }
        #pragma unroll
        for (int k = 0; k < 4; k++) {
            int t = s + 256 * k;
            Bf[WRO + (t & 31) * XS + (t >> 5)] = __ldg(gr + t);
        }
        if (s < 128) {
            int q = s >> 5, i = s & 31;
            const float* bp = (q == 0) ? dil_b : (q == 1) ? filt_b : (q == 2) ? gate_b : res_b;
            Bf[BSO + s] = __ldg(bp + li * 32 + i);
        }
    };

    // ================= init: embedding + init conv, split by rank =========
    if (warp < 16) {
        const int ilo = rank ? 38 : 0;
        const int ihi = rank ? 76 : 39;
        if (tid < 77) stok[tid] = tokens[b * T_LEN + (T_LEN - 77) + tid];
        float* WI = RB;                      // [e][c] stride XS (3600 fl in RB+GT)
        for (int t = tid; t < 3200; t += 512)
            WI[(t % 100) * XS + (t / 100)] = init_w[t];
        asm volatile("bar.sync 1, 512;");
        float* SE = sm + OFF_WB + 2 * WBSZ;  // [p][e] stride SESTR in buf2
        for (int t = tid; t < 7700; t += 512) {
            int p = t / 100, e = t - p * 100;
            SE[p * SESTR + e] = emb[stok[p] * 100 + e];
        }
        asm volatile("bar.sync 1, 512;");
        #pragma unroll
        for (int pass = 0; pass < 2; pass++) {
            int u = lane + 32 * pg + 64 * pass;
            int blo = 32 * pg + 64 * pass, bhi = blo + 31;
            if (bhi >= ilo && blo <= ihi) {
                bool v = (u >= ilo && u <= ihi);
                int uu = v ? u : ilo;
                u64 a0 = pack2(init_b[cb],   init_b[cb+1]);
                u64 a1 = pack2(init_b[cb+2], init_b[cb+3]);
                const float* xr = &SE[uu * SESTR];
                #pragma unroll 5
                for (int e = 0; e < 100; e += 4) {
                    float4 xv = *(const float4*)(xr + e);
                    #pragma unroll
                    for (int ee = 0; ee < 4; ee++) {
                        u64 d0 = dup2((&xv.x)[ee]);
                        ulonglong2 Wv = *(const ulonglong2*)&WI[(e + ee)*XS + cb];
                        fma2(a0, Wv.x, d0); fma2(a1, Wv.y, d0);
                    }
                }
                if (v) { ulonglong2 t0; t0.x = a0; t0.y = a1;
                         *(ulonglong2*)&X0[u*XS + cb] = t0; }
            }
        }
    } else {
        stage(0, 0);
        stage(1, 1);
    }
    __syncthreads();

    // ================= 16 dilated layers =================================
    int W = 75;
    int cur = 0;
    #pragma unroll 1
    for (int li = 0; li < 16; li++) {
        const int d = 1 << (li & 3);
        if (li) W -= d + 1;
        const int c    = d_cArr[li];
        const int Bp   = rank ? c : 0;
        const int hiRB = rank ? W : c;
        const int hiGT = hiRB - 1;
        float* Xr = (li & 1) ? X1 : X0;
        float* Xw = (li & 1) ? X0 : X1;
        const int xwoff = (li & 1) ? OFF_X0 : OFF_X1;

        float* WBp = sm + OFF_WB + cur * WBSZ;
        const float* WD  = WBp + WDO;
        const float* WF  = WBp + WFO;
        const float* WG  = WBp + WGO;
        const float* WRs = WBp + WRO;
        const float* BS  = WBp + BSO;

        if (warp >= 16 && li < 14) {
            int bi = cur + 2; if (bi >= 3) bi -= 3;
            stage(li + 2, bi);
        }

        const bool possplit = (li < 3);

        // ---- dil -> RB ----
        if (warp < 16) {
            if (possplit) {
                const int u = Bp + lane + 32 * pg;
                const bool v = (u <= hiRB); const int uu = v ? u : Bp;
                u64 a0 = pack2(BS[cb], BS[cb+1]);
                u64 a1 = pack2(BS[cb+2], BS[cb+3]);
                u64 c0 = dup2(0.f), c1 = dup2(0.f);
                const float* q0 = &Xr[uu*XS];
                const float* q1 = &Xr[(uu + d)*XS];
                #pragma unroll
                for (int r = 0; r < 32; r += 4) {
                    float4 xa = *(const float4*)(q0 + r);
                    float4 xb = *(const float4*)(q1 + r);
                    #pragma unroll
                    for (int rr = 0; rr < 4; rr++) {
                        const float* w = &WD[(2*(r + rr))*XS + cb];
                        ulonglong2 W0 = *(const ulonglong2*)w;
                        ulonglong2 W1 = *(const ulonglong2*)(w + XS);
                        u64 dA = dup2((&xa.x)[rr]), dB = dup2((&xb.x)[rr]);
                        fma2(a0, W0.x, dA); fma2(a1, W0.y, dA);
                        fma2(c0, W1.x, dB); fma2(c1, W1.y, dB);
                    }
                }
                if (v) { ulonglong2 t0; t0.x = add2(a0, c0); t0.y = add2(a1, c1);
                         *(ulonglong2*)&RB[u*XS + cb] = t0; }
            } else {
                const int u = Bp + lane;
                const bool v = (u <= hiRB); const int uu = v ? u : Bp;
                const int rB = pg << 4;
                u64 a0, a1;
                if (pg == 0) { a0 = pack2(BS[cb], BS[cb+1]); a1 = pack2(BS[cb+2], BS[cb+3]); }
                else         { a0 = dup2(0.f); a1 = dup2(0.f); }
                u64 c0 = dup2(0.f), c1 = dup2(0.f);
                const float* q0 = &Xr[uu*XS + rB];
                const float* q1 = &Xr[(uu + d)*XS + rB];
                #pragma unroll
                for (int r = 0; r < 16; r += 4) {
                    float4 xa = *(const float4*)(q0 + r);
                    float4 xb = *(const float4*)(q1 + r);
                    #pragma unroll
                    for (int rr = 0; rr < 4; rr++) {
                        const float* w = &WD[(2*(rB + r + rr))*XS + cb];
                        ulonglong2 W0 = *(const ulonglong2*)w;
                        ulonglong2 W1 = *(const ulonglong2*)(w + XS);
                        u64 dA = dup2((&xa.x)[rr]), dB = dup2((&xb.x)[rr]);
                        fma2(a0, W0.x, dA); fma2(a1, W0.y, dA);
                        fma2(c0, W1.x, dB); fma2(c1, W1.y, dB);
                    }
                }
                a0 = add2(a0, c0); a1 = add2(a1, c1);
                if (pg) { ulonglong2 t0; t0.x = a0; t0.y = a1;
                          *(ulonglong2*)&PB[lane*XS + cb] = t0; }
                asm volatile("bar.sync 2, 512;" ::: "memory");
                if (!pg) {
                    ulonglong2 pp = *(const ulonglong2*)&PB[lane*XS + cb];
                    if (v) { ulonglong2 t0; t0.x = add2(a0, pp.x); t0.y = add2(a1, pp.y);
                             *(ulonglong2*)&RB[u*XS + cb] = t0; }
                }
            }
        }
        __syncthreads();

        // ---- filter & gate + activation -> GT ----
        if (warp < 16) {
            if (possplit) {
                const int u = Bp + lane + 32 * pg;
                const bool v = (u <= hiGT); const int uu = v ? u : Bp;
                u64 f0 = pack2(BS[32+cb], BS[32+cb+1]);
                u64 f1 = pack2(BS[32+cb+2], BS[32+cb+3]);
                u64 g0 = pack2(BS[64+cb], BS[64+cb+1]);
                u64 g1 = pack2(BS[64+cb+2], BS[64+cb+3]);
                u64 h0 = dup2(0.f), h1 = dup2(0.f);
                u64 k0 = dup2(0.f), k1 = dup2(0.f);
                const float* q0 = &RB[uu*XS];
                const float* q1 = &RB[(uu + 1)*XS];
                #pragma unroll
                for (int r = 0; r < 32; r += 4) {
                    float4 xa = *(const float4*)(q0 + r);
                    float4 xb = *(const float4*)(q1 + r);
                    #pragma unroll
                    for (int rr = 0; rr < 4; rr++) {
                        u64 dA = dup2((&xa.x)[rr]), dB = dup2((&xb.x)[rr]);
                        const float* wf = &WF[(2*(r + rr))*XS + cb];
                        ulonglong2 F0 = *(const ulonglong2*)wf;
                        ulonglong2 F1 = *(const ulonglong2*)(wf + XS);
                        fma2(f0, F0.x, dA); fma2(f1, F0.y, dA);
                        fma2(h0, F1.x, dB); fma2(h1, F1.y, dB);
                        const float* wg = &WG[(2*(r + rr))*XS + cb];
                        ulonglong2 G0 = *(const ulonglong2*)wg;
                        ulonglong2 G1 = *(const ulonglong2*)(wg + XS);
                        fma2(g0, G0.x, dA); fma2(g1, G0.y, dA);
                        fma2(k0, G1.x, dB); fma2(k1, G1.y, dB);
                    }
                }
                if (v) {
                    f0 = add2(f0, h0); f1 = add2(f1, h1);
                    g0 = add2(g0, k0); g1 = add2(g1, k1);
                    float2 Fa = unpk(f0), Fb = unpk(f1);
                    float2 Ga = unpk(g0), Gb = unpk(g1);
                    float4 o;
                    o.x = fast_tanh(Fa.x) * fast_sig(Ga.x);
                    o.y = fast_tanh(Fa.y) * fast_sig(Ga.y);
                    o.z = fast_tanh(Fb.x) * fast_sig(Gb.x);
                    o.w = fast_tanh(Fb.y) * fast_sig(Gb.y);
                    *(float4*)&GT[u*XS + cb] = o;
                }
            } else {
                const int u = Bp + lane;
                const bool v = (u <= hiGT); const int uu = v ? u : Bp;
                const int rB = pg << 4;
                u64 f0, f1, g0, g1;
                if (pg == 0) {
                    f0 = pack2(BS[32+cb], BS[32+cb+1]); f1 = pack2(BS[32+cb+2], BS[32+cb+3]);
                    g0 = pack2(BS[64+cb], BS[64+cb+1]); g1 = pack2(BS[64+cb+2], BS[64+cb+3]);
                } else { f0 = f1 = g0 = g1 = dup2(0.f); }
                u64 h0 = dup2(0.f), h1 = dup2(0.f);
                u64 k0 = dup2(0.f), k1 = dup2(0.f);
                const float* q0 = &RB[uu*XS + rB];
                const float* q1 = &RB[(uu + 1)*XS + rB];
                #pragma unroll
                for (int r = 0; r < 16; r += 4) {
                    float4 xa = *(const float4*)(q0 + r);
                    float4 xb = *(const float4*)(q1 + r);
                    #pragma unroll
                    for (int rr = 0; rr < 4; rr++) {
                        u64 dA = dup2((&xa.x)[rr]), dB = dup2((&xb.x)[rr]);
                        const float* wf = &WF[(2*(rB + r + rr))*XS + cb];
                        ulonglong2 F0 = *(const ulonglong2*)wf;
                        ulonglong2 F1 = *(const ulonglong2*)(wf + XS);
                        fma2(f0, F0.x, dA); fma2(f1, F0.y, dA);
                        fma2(h0, F1.x, dB); fma2(h1, F1.y, dB);
                        const float* wg = &WG[(2*(rB + r + rr))*XS + cb];
                        ulonglong2 G0 = *(const ulonglong2*)wg;
                        ulonglong2 G1 = *(const ulonglong2*)(wg + XS);
                        fma2(g0, G0.x, dA); fma2(g1, G0.y, dA);
                        fma2(k0, G1.x, dB); fma2(k1, G1.y, dB);
                    }
                }
                f0 = add2(f0, h0); f1 = add2(f1, h1);
                g0 = add2(g0, k0); g1 = add2(g1, k1);
                if (pg) {
                    ulonglong2 t0; t0.x = f0; t0.y = f1;
                    *(ulonglong2*)&PB[lane*XS + cb] = t0;
                    ulonglong2 t1; t1.x = g0; t1.y = g1;
                    *(ulonglong2*)&PB[(lane + 32)*XS + cb] = t1;
                }
                asm volatile("bar.sync 2, 512;" ::: "memory");
                if (!pg && v) {
                    ulonglong2 pf = *(const ulonglong2*)&PB[lane*XS + cb];
                    ulonglong2 pgv = *(const ulonglong2*)&PB[(lane + 32)*XS + cb];
                    f0 = add2(f0, pf.x);  f1 = add2(f1, pf.y);
                    g0 = add2(g0, pgv.x); g1 = add2(g1, pgv.y);
                    float2 Fa = unpk(f0), Fb = unpk(f1);
                    float2 Ga = unpk(g0), Gb = unpk(g1);
                    float4 o;
                    o.x = fast_tanh(Fa.x) * fast_sig(Ga.x);
                    o.y = fast_tanh(Fa.y) * fast_sig(Ga.y);
                    o.z = fast_tanh(Fb.x) * fast_sig(Gb.x);
                    o.w = fast_tanh(Fb.y) * fast_sig(Gb.y);
                    *(float4*)&GT[u*XS + cb] = o;
                }
            }
        }
        __syncthreads();

        // ---- res + residual -> Xw ----
        if (li < 15 && warp < 16) {
            if (possplit) {
                const int u = Bp + lane + 32 * pg;
                const bool v = (u <= hiGT); const int uu = v ? u : Bp;
                u64 a0 = pack2(BS[96+cb], BS[96+cb+1]);
                u64 a1 = pack2(BS[96+cb+2], BS[96+cb+3]);
                u64 c0 = dup2(0.f), c1 = dup2(0.f);
                const float* q0 = &GT[uu*XS];
                #pragma unroll
                for (int r = 0; r < 32; r += 8) {
                    float4 xa = *(const float4*)(q0 + r);
                    float4 xb = *(const float4*)(q0 + r + 4);
                    #pragma unroll
                    for (int rr = 0; rr < 4; rr++) {
                        u64 d0 = dup2((&xa.x)[rr]), d1 = dup2((&xb.x)[rr]);
                        ulonglong2 W0 = *(const ulonglong2*)&WRs[(r + rr)*XS + cb];
                        ulonglong2 W1 = *(const ulonglong2*)&WRs[(r + rr + 4)*XS + cb];
                        fma2(a0, W0.x, d0); fma2(a1, W0.y, d0);
                        fma2(c0, W1.x, d1); fma2(c1, W1.y, d1);
                    }
                }
                if (v) {
                    ulonglong2 rv = *(const ulonglong2*)&RB[u*XS + cb];
                    ulonglong2 t0;
                    t0.x = add2(add2(a0, c0), rv.x);
                    t0.y = add2(add2(a1, c1), rv.y);
                    *(ulonglong2*)&Xw[u*XS + cb] = t0;
                }
            } else {
                const int u = Bp + lane;
                const bool v = (u <= hiGT); const int uu = v ? u : Bp;
                const int rB = pg << 4;
                u64 a0, a1;
                if (pg == 0) { a0 = pack2(BS[96+cb], BS[96+cb+1]); a1 = pack2(BS[96+cb+2], BS[96+cb+3]); }
                else         { a0 = dup2(0.f); a1 = dup2(0.f); }
                u64 c0 = dup2(0.f), c1 = dup2(0.f);
                const float* q0 = &GT[uu*XS + rB];
                #pragma unroll
                for (int r = 0; r < 16; r += 8) {
                    float4 xa = *(const float4*)(q0 + r);
                    float4 xb = *(const float4*)(q0 + r + 4);
                    #pragma unroll
                    for (int rr = 0; rr < 4; rr++) {
                        u64 d0 = dup2((&xa.x)[rr]), d1 = dup2((&xb.x)[rr]);
                        ulonglong2 W0 = *(const ulonglong2*)&WRs[(rB + r + rr)*XS + cb];
                        ulonglong2 W1 = *(const ulonglong2*)&WRs[(rB + r + rr + 4)*XS + cb];
                        fma2(a0, W0.x, d0); fma2(a1, W0.y, d0);
                        fma2(c0, W1.x, d1); fma2(c1, W1.y, d1);
                    }
                }
                a0 = add2(a0, c0); a1 = add2(a1, c1);
                if (pg) { ulonglong2 t0; t0.x = a0; t0.y = a1;
                          *(ulonglong2*)&PB[lane*XS + cb] = t0; }
                asm volatile("bar.sync 2, 512;" ::: "memory");
                if (!pg && v) {
                    ulonglong2 pp = *(const ulonglong2*)&PB[lane*XS + cb];
                    ulonglong2 rv = *(const ulonglong2*)&RB[u*XS + cb];
                    ulonglong2 t0;
                    t0.x = add2(add2(a0, pp.x), rv.x);
                    t0.y = add2(add2(a1, pp.y), rv.y);
                    *(ulonglong2*)&Xw[u*XS + cb] = t0;
                }
            }
        }
        __syncthreads();

        // ---- halo exchange + cluster sync ----
        if (li < 15) {
            if (warp == 0) {
                const int lo = rank ? d_R0LO[li] : d_R1LO[li];
                const int hi = rank ? d_R0HI[li] : d_R1HI[li];
                const int n  = (hi - lo + 1) * 16;
                for (int i = lane; i < n; i += 32) {
                    int p  = lo + (i >> 4);
                    int of = (i & 15) << 1;
                    u64 vv = *(const u64*)(Xw + p*XS + of);
                    uint32_t la = smem_u32 + (uint32_t)(xwoff + p*XS + of) * 4u;
                    uint32_t ra;
                    asm volatile("mapa.shared::cluster.u32 %0, %1, %2;"
                                 : "=r"(ra) : "r"(la), "r"(peer));
                    asm volatile("st.shared::cluster.b64 [%0], %1;"
                                 :: "r"(ra), "l"(vv) : "memory");
                }
            }
            asm volatile("barrier.cluster.arrive.aligned;" ::: "memory");
            asm volatile("barrier.cluster.wait.aligned;" ::: "memory");
        }
        cur++; if (cur == 3) cur = 0;
    }

    // ================= tail (rank 0 only): skip/end/fc at t = T-1 =========
    if (rank == 0) {
        float* SV = RB;
        float* H1 = RB + 256;
        float* H2 = RB + 512;
        float* F1 = RB + 768;
        float* F2 = RB + 896;
        float* F3 = RB + 1024;

        const float* skw = skip_w + 15*256*32;
        const float* skb = skip_b + 15*256;
        float gv = GT[lane];
        #pragma unroll 2
        for (int o = warp; o < 256; o += 24) {
            float v = __ldg(&skw[o*32 + lane]) * gv;
            v = warp_sum(v);
            if (lane == 0) SV[o] = fmaxf(v + skb[o], 0.f);
        }
        __syncthreads();
        #pragma unroll 2
        for (int o = warp; o < 256; o += 24) {
            const float4* wp = (const float4*)(end1_w + o*256);
            const float4* sp = (const float4*)SV;
            float v = dot4(__ldg(wp + lane), sp[lane]) + dot4(__ldg(wp + lane + 32), sp[lane + 32]);
            v = warp_sum(v);
            if (lane == 0) H1[o] = fmaxf(v + end1_b[o], 0.f);
        }
        __syncthreads();
        #pragma unroll 2
        for (int o = warp; o < 256; o += 24) {
            const float4* wp = (const float4*)(end2_w + o*256);
            const float4* sp = (const float4*)H1;
            float v = dot4(__ldg(wp + lane), sp[lane]) + dot4(__ldg(wp + lane + 32), sp[lane + 32]);
            v = warp_sum(v);
            if (lane == 0) H2[o] = v + end2_b[o];
        }
        __syncthreads();
        #pragma unroll 2
        for (int o = warp; o < 128; o += 24) {
            const float4* wp = (const float4*)(fc1_w + o*256);
            const float4* sp = (const float4*)H2;
            float v = dot4(__ldg(wp + lane), sp[lane]) + dot4(__ldg(wp + lane + 32), sp[lane + 32]);
            v = warp_sum(v);
            if (lane == 0) F1[o] = fmaxf(v + fc1_b[o], 0.f);
        }
        __syncthreads();
        #pragma unroll 2
        for (int o = warp; o < 128; o += 24) {
            const float4* wp = (const float4*)(fc2_w + o*128);
            const float4* sp = (const float4*)F1;
            float v = dot4(__ldg(wp + lane), sp[lane]);
            v = warp_sum(v);
            if (lane == 0) F2[o] = fmaxf(v + fc2_b[o], 0.f);
        }
        __syncthreads();
        #pragma unroll 2
        for (int o = warp; o < 64; o += 24) {
            const float4* wp = (const float4*)(fc3_w + o*128);
            const float4* sp = (const float4*)F2;
            float v = dot4(__ldg(wp + lane), sp[lane]);
            v = warp_sum(v);
            if (lane == 0) F3[o] = fmaxf(v + fc3_b[o], 0.f);
        }
        __syncthreads();
        #pragma unroll 2
        for (int o = warp; o < 256; o += 24) {
            const float2* wp = (const float2*)(fc4_w + o*64);
            const float2* sp = (const float2*)F3;
            float2 wv = __ldg(wp + lane);
            float2 sv = sp[lane];
            float v = fmaf(wv.x, sv.x, wv.y * sv.y);
            v = warp_sum(v);
            if (lane == 0) out[b*256 + o] = v + fc4_b[o];
        }
    }
}

extern "C" void kernel_launch(void* const* d_in, const int* in_sizes, int n_in,
                              void* d_out, int out_size)
{
    (void)in_sizes; (void)n_in; (void)out_size;
    const size_t smem_bytes = (size_t)SMEM_FLOATS * sizeof(float);
    cudaFuncSetAttribute(wavenet_kernel, cudaFuncAttributeMaxDynamicSharedMemorySize,
                         (int)smem_bytes);
    wavenet_kernel<<<32, NT, smem_bytes>>>(
        (const int*)  d_in[0],  (const float*)d_in[1],
        (const float*)d_in[2],  (const float*)d_in[3],
        (const float*)d_in[4],  (const float*)d_in[5],
        (const float*)d_in[6],  (const float*)d_in[7],
        (const float*)d_in[8],  (const float*)d_in[9],
        (const float*)d_in[10], (const float*)d_in[11],
        (const float*)d_in[12], (const float*)d_in[13],
        (const float*)d_in[14], (const float*)d_in[15],
        (const float*)d_in[16], (const float*)d_in[17],
        (const float*)d_in[18], (const float*)d_in[19],
        (const float*)d_in[20], (const float*)d_in[21],
        (const float*)d_in[22], (const float*)d_in[23],
        (const float*)d_in[24], (const float*)d_in[25],
        (float*)d_out);
}

// round 15
// speedup vs baseline: 1.5266x; 1.5266x over previous
#include <cuda_runtime.h>
#include <stdint.h>
#include <math.h>

#define T_LEN 8192
#define NT 768
#define XS 36          // padded row stride: 16B-aligned, phase-conflict-free
#define SESTR 104

// float offsets in dynamic smem
#define OFF_X   0          // 77 x XS
#define OFF_RB  2772       // 76 x XS
#define OFF_GT  5508       // 75 x XS
#define OFF_PB  8208       // 128 x XS partial scratch (f:0-63, g:64-127)
#define OFF_WB  12816      // 3 weight buffers
#define WBSZ    8192
#define WDO 0
#define WFO 2304
#define WGO 4608
#define WRO 6912
#define BSO 8064
#define SMEM_FLOATS (OFF_WB + 3*WBSZ)   // 37392 floats = 149568 B

typedef unsigned long long u64;

__device__ __forceinline__ u64 pack2(float lo, float hi) {
    u64 r; asm("mov.b64 %0,{%1,%2};" : "=l"(r) : "f"(lo), "f"(hi)); return r;
}
__device__ __forceinline__ u64 dup2(float x) { return pack2(x, x); }
__device__ __forceinline__ void fma2(u64& a, u64 w, u64 x) {
    asm("fma.rn.f32x2 %0,%1,%2,%0;" : "+l"(a) : "l"(w), "l"(x));
}
__device__ __forceinline__ u64 add2(u64 a, u64 b) {
    u64 r; asm("add.rn.f32x2 %0,%1,%2;" : "=l"(r) : "l"(a), "l"(b)); return r;
}
__device__ __forceinline__ float2 unpk(u64 a) {
    float2 f; asm("mov.b64 {%0,%1},%2;" : "=f"(f.x), "=f"(f.y) : "l"(a)); return f;
}
__device__ __forceinline__ float warp_sum(float v) {
    #pragma unroll
    for (int o = 16; o; o >>= 1) v += __shfl_xor_sync(0xffffffffu, v, o);
    return v;
}
__device__ __forceinline__ float fast_tanh(float x) {
    float e = __expf(-2.0f * x);
    return fmaf(2.0f, __frcp_rn(1.0f + e), -1.0f);
}
__device__ __forceinline__ float fast_sig(float x) {
    return __frcp_rn(1.0f + __expf(-x));
}
__device__ __forceinline__ float dot4(float4 a, float4 b) {
    return fmaf(a.x, b.x, fmaf(a.y, b.y, fmaf(a.z, b.z, a.w * b.w)));
}

__global__ void __launch_bounds__(NT, 1) wavenet_kernel(
    const int*   __restrict__ tokens,
    const float* __restrict__ emb,
    const float* __restrict__ init_w, const float* __restrict__ init_b,
    const float* __restrict__ dil_w,  const float* __restrict__ dil_b,
    const float* __restrict__ filt_w, const float* __restrict__ filt_b,
    const float* __restrict__ gate_w, const float* __restrict__ gate_b,
    const float* __restrict__ res_w,  const float* __restrict__ res_b,
    const float* __restrict__ skip_w, const float* __restrict__ skip_b,
    const float* __restrict__ end1_w, const float* __restrict__ end1_b,
    const float* __restrict__ end2_w, const float* __restrict__ end2_b,
    const float* __restrict__ fc1_w,  const float* __restrict__ fc1_b,
    const float* __restrict__ fc2_w,  const float* __restrict__ fc2_b,
    const float* __restrict__ fc3_w,  const float* __restrict__ fc3_b,
    const float* __restrict__ fc4_w,  const float* __restrict__ fc4_b,
    float* __restrict__ out)
{
    extern __shared__ float sm[];
    __shared__ int stok[77];

    float* X   = sm + OFF_X;
    float* RB  = sm + OFF_RB;
    float* GT  = sm + OFF_GT;
    float* PB  = sm + OFF_PB;            // partials (f / generic)
    float* PBG = sm + OFF_PB + 64*XS;    // partials (g)

    const int b    = blockIdx.x;
    const int tid  = threadIdx.x;
    const int lane = tid & 31;
    const int warp = tid >> 5;
    const int cg   = warp & 7;
    const int pg   = (warp >> 3) & 1;
    const int cb   = cg * 4;
    const int s    = tid - 512;

    auto stage = [&](int li, int bi) {
        float* Bf = sm + OFF_WB + bi * WBSZ;
        const float* gd = dil_w  + li * 2048;
        const float* gf = filt_w + li * 2048;
        const float* gg = gate_w + li * 2048;
        const float* gr = res_w  + li * 1024;
        #pragma unroll
        for (int k = 0; k < 8; k++) {
            int t = s + 256 * k;
            int c = t >> 6, rk = t & 63;
            int o = rk * XS + c;
            Bf[WDO + o] = __ldg(gd + t);
            Bf[WFO + o] = __ldg(gf + t);
            Bf[WGO + o] = __ldg(gg + t);
        }
        #pragma unroll
        for (int k = 0; k < 4; k++) {
            int t = s + 256 * k;
            Bf[WRO + (t & 31) * XS + (t >> 5)] = __ldg(gr + t);
        }
        if (s < 128) {
            int q = s >> 5, i = s & 31;
            const float* bp = (q == 0) ? dil_b : (q == 1) ? filt_b : (q == 2) ? gate_b : res_b;
            Bf[BSO + s] = __ldg(bp + li * 32 + i);
        }
    };

    // ================= init =================
    if (warp < 16) {
        const int iu0 = lane + 32 * pg;
        const int iu1 = iu0 + 64;
        if (tid < 77) stok[tid] = tokens[b * T_LEN + (T_LEN - 77) + tid];
        float* WI = RB;                      // [e][c] stride XS
        for (int t = tid; t < 3200; t += 512)
            WI[(t % 100) * XS + (t / 100)] = init_w[t];
        asm volatile("bar.sync 1, 512;");
        float* SE = sm + OFF_WB + 2 * WBSZ;  // [p][e] stride SESTR in buf2
        for (int t = tid; t < 7700; t += 512) {
            int p = t / 100, e = t - p * 100;
            SE[p * SESTR + e] = emb[stok[p] * 100 + e];
        }
        asm volatile("bar.sync 1, 512;");
        {
            const int v1 = (iu1 < 77);
            const int uu1 = v1 ? iu1 : 0;
            u64 a0 = pack2(init_b[cb],   init_b[cb+1]);
            u64 a1 = pack2(init_b[cb+2], init_b[cb+3]);
            u64 b0 = a0, b1 = a1;
            const float* xr0 = &SE[iu0 * SESTR];
            const float* xr1 = &SE[uu1 * SESTR];
            #pragma unroll 5
            for (int e = 0; e < 100; e += 4) {
                float4 x0 = *(const float4*)(xr0 + e);
                float4 x1 = *(const float4*)(xr1 + e);
                #pragma unroll
                for (int ee = 0; ee < 4; ee++) {
                    u64 d0 = dup2((&x0.x)[ee]);
                    u64 d1 = dup2((&x1.x)[ee]);
                    ulonglong2 Wv = *(const ulonglong2*)&WI[(e + ee)*XS + cb];
                    fma2(a0, Wv.x, d0); fma2(a1, Wv.y, d0);
                    fma2(b0, Wv.x, d1); fma2(b1, Wv.y, d1);
                }
            }
            { ulonglong2 t0; t0.x = a0; t0.y = a1; *(ulonglong2*)&X[iu0*XS + cb] = t0; }
            if (v1) { ulonglong2 t0; t0.x = b0; t0.y = b1; *(ulonglong2*)&X[iu1*XS + cb] = t0; }
        }
    } else {
        stage(0, 0);
        stage(1, 1);
    }
    __syncthreads();

    // ================= 16 dilated layers =================
    int W = 75;
    int cur = 0;
    #pragma unroll 1
    for (int li = 0; li < 16; li++) {
        const int d = 1 << (li & 3);
        if (li) W -= d + 1;
        const int mode = (W > 63) ? 0 : ((W > 31) ? 1 : 2);

        float* WBp = sm + OFF_WB + cur * WBSZ;
        const float* WD  = WBp + WDO;
        const float* WF  = WBp + WFO;
        const float* WG  = WBp + WGO;
        const float* WRs = WBp + WRO;
        const float* BS  = WBp + BSO;

        if (warp >= 16 && li < 14) {
            int bi = cur + 2; if (bi >= 3) bi -= 3;
            stage(li + 2, bi);
        }

        // ---- dilated conv -> RB ----
        if (warp < 16) {
            if (mode == 0) {
                const int u0 = lane + 32 * pg, u1 = u0 + 64;
                const bool v1 = (u1 <= W);
                const int uu1 = v1 ? u1 : 0;
                u64 a0 = pack2(BS[cb], BS[cb+1]);
                u64 a1 = pack2(BS[cb+2], BS[cb+3]);
                u64 b0 = a0, b1 = a1;
                const float* p00 = &X[u0*XS];
                const float* p01 = &X[(u0 + d)*XS];
                const float* p10 = &X[uu1*XS];
                const float* p11 = &X[(uu1 + d)*XS];
                #pragma unroll
                for (int r = 0; r < 32; r += 4) {
                    float4 xa0 = *(const float4*)(p00 + r);
                    float4 xb0 = *(const float4*)(p01 + r);
                    float4 xa1 = *(const float4*)(p10 + r);
                    float4 xb1 = *(const float4*)(p11 + r);
                    #pragma unroll
                    for (int rr = 0; rr < 4; rr++) {
                        const float* w = &WD[(2*(r + rr))*XS + cb];
                        ulonglong2 W0 = *(const ulonglong2*)w;
                        ulonglong2 W1 = *(const ulonglong2*)(w + XS);
                        u64 d00 = dup2((&xa0.x)[rr]), d01 = dup2((&xb0.x)[rr]);
                        u64 d10 = dup2((&xa1.x)[rr]), d11 = dup2((&xb1.x)[rr]);
                        fma2(a0, W0.x, d00); fma2(a1, W0.y, d00);
                        fma2(a0, W1.x, d01); fma2(a1, W1.y, d01);
                        fma2(b0, W0.x, d10); fma2(b1, W0.y, d10);
                        fma2(b0, W1.x, d11); fma2(b1, W1.y, d11);
                    }
                }
                { ulonglong2 t0; t0.x = a0; t0.y = a1; *(ulonglong2*)&RB[u0*XS + cb] = t0; }
                if (v1) { ulonglong2 t0; t0.x = b0; t0.y = b1; *(ulonglong2*)&RB[u1*XS + cb] = t0; }
            } else {
                // r-split: pg0 rows 0-15 (+bias), pg1 rows 16-31; 1-2 positions
                const int rB = pg << 4;
                const int u0 = lane, u1 = lane + 32;
                const bool dual = (mode == 1);
                const bool v0 = (u0 <= W);
                const bool v1 = dual && (u1 <= W);
                const int uu0 = v0 ? u0 : 0;
                const int uu1 = v1 ? u1 : 0;
                u64 a0, a1;
                if (pg == 0) { a0 = pack2(BS[cb], BS[cb+1]); a1 = pack2(BS[cb+2], BS[cb+3]); }
                else         { a0 = dup2(0.f); a1 = dup2(0.f); }
                // BUGFIX R13: in dual mode pos1 accumulator must carry the bias
                // exactly once (pg0's a0 holds it, pg1's a0 is zero).
                u64 b0, b1;
                if (dual) { b0 = a0; b1 = a1; }
                else      { b0 = dup2(0.f); b1 = dup2(0.f); }
                const float* q00 = &X[uu0*XS + rB];
                const float* q01 = &X[(uu0 + d)*XS + rB];
                const float* q10 = &X[uu1*XS + rB];
                const float* q11 = &X[(uu1 + d)*XS + rB];
                if (dual) {
                    #pragma unroll
                    for (int r = 0; r < 16; r += 4) {
                        float4 xa0 = *(const float4*)(q00 + r);
                        float4 xb0 = *(const float4*)(q01 + r);
                        float4 xa1 = *(const float4*)(q10 + r);
                        float4 xb1 = *(const float4*)(q11 + r);
                        #pragma unroll
                        for (int rr = 0; rr < 4; rr++) {
                            const float* w = &WD[(2*(rB + r + rr))*XS + cb];
                            ulonglong2 W0 = *(const ulonglong2*)w;
                            ulonglong2 W1 = *(const ulonglong2*)(w + XS);
                            u64 d00 = dup2((&xa0.x)[rr]), d01 = dup2((&xb0.x)[rr]);
                            u64 d10 = dup2((&xa1.x)[rr]), d11 = dup2((&xb1.x)[rr]);
                            fma2(a0, W0.x, d00); fma2(a1, W0.y, d00);
                            fma2(a0, W1.x, d01); fma2(a1, W1.y, d01);
                            fma2(b0, W0.x, d10); fma2(b1, W0.y, d10);
                            fma2(b0, W1.x, d11); fma2(b1, W1.y, d11);
                        }
                    }
                } else {
                    #pragma unroll
                    for (int r = 0; r < 16; r += 4) {
                        float4 xa0 = *(const float4*)(q00 + r);
                        float4 xb0 = *(const float4*)(q01 + r);
                        #pragma unroll
                        for (int rr = 0; rr < 4; rr++) {
                            const float* w = &WD[(2*(rB + r + rr))*XS + cb];
                            ulonglong2 W0 = *(const ulonglong2*)w;
                            ulonglong2 W1 = *(const ulonglong2*)(w + XS);
                            u64 d00 = dup2((&xa0.x)[rr]), d01 = dup2((&xb0.x)[rr]);
                            fma2(a0, W0.x, d00); fma2(a1, W0.y, d00);
                            fma2(b0, W1.x, d01); fma2(b1, W1.y, d01);
                        }
                    }
                    a0 = add2(a0, b0); a1 = add2(a1, b1);
                }
                if (pg) {
                    { ulonglong2 t0; t0.x = a0; t0.y = a1; *(ulonglong2*)&PB[u0*XS + cb] = t0; }
                    if (dual) { ulonglong2 t0; t0.x = b0; t0.y = b1; *(ulonglong2*)&PB[u1*XS + cb] = t0; }
                }
                asm volatile("bar.sync 2, 512;" ::: "memory");
                if (!pg) {
                    if (v0) {
                        ulonglong2 pp = *(const ulonglong2*)&PB[u0*XS + cb];
                        ulonglong2 t0; t0.x = add2(a0, pp.x); t0.y = add2(a1, pp.y);
                        *(ulonglong2*)&RB[u0*XS + cb] = t0;
                    }
                    if (v1) {
                        ulonglong2 pp = *(const ulonglong2*)&PB[u1*XS + cb];
                        ulonglong2 t0; t0.x = add2(b0, pp.x); t0.y = add2(b1, pp.y);
                        *(ulonglong2*)&RB[u1*XS + cb] = t0;
                    }
                }
            }
        }
        __syncthreads();

        // ---- filter & gate + activation -> GT ----
        if (warp < 16) {
            if (mode == 0) {
                const int u0 = lane + 32 * pg, u1 = u0 + 64;
                const bool v1 = (u1 < W);
                const int uu1 = v1 ? u1 : 0;
                u64 f0 = pack2(BS[32+cb], BS[32+cb+1]);
                u64 f1 = pack2(BS[32+cb+2], BS[32+cb+3]);
                u64 g0 = pack2(BS[64+cb], BS[64+cb+1]);
                u64 g1 = pack2(BS[64+cb+2], BS[64+cb+3]);
                u64 h0 = f0, h1 = f1;
                u64 k0 = g0, k1 = g1;
                const float* p00 = &RB[u0*XS];
                const float* p01 = &RB[(u0 + 1)*XS];
                const float* p10 = &RB[uu1*XS];
                const float* p11 = &RB[(uu1 + 1)*XS];
                #pragma unroll
                for (int r = 0; r < 32; r += 4) {
                    float4 xa0 = *(const float4*)(p00 + r);
                    float4 xb0 = *(const float4*)(p01 + r);
                    float4 xa1 = *(const float4*)(p10 + r);
                    float4 xb1 = *(const float4*)(p11 + r);
                    #pragma unroll
                    for (int rr = 0; rr < 4; rr++) {
                        u64 d00 = dup2((&xa0.x)[rr]), d01 = dup2((&xb0.x)[rr]);
                        u64 d10 = dup2((&xa1.x)[rr]), d11 = dup2((&xb1.x)[rr]);
                        const float* wf = &WF[(2*(r + rr))*XS + cb];
                        ulonglong2 F0 = *(const ulonglong2*)wf;
                        ulonglong2 F1 = *(const ulonglong2*)(wf + XS);
                        fma2(f0, F0.x, d00); fma2(f1, F0.y, d00);
                        fma2(f0, F1.x, d01); fma2(f1, F1.y, d01);
                        fma2(h0, F0.x, d10); fma2(h1, F0.y, d10);
                        fma2(h0, F1.x, d11); fma2(h1, F1.y, d11);
                        const float* wg = &WG[(2*(r + rr))*XS + cb];
                        ulonglong2 G0 = *(const ulonglong2*)wg;
                        ulonglong2 G1 = *(const ulonglong2*)(wg + XS);
                        fma2(g0, G0.x, d00); fma2(g1, G0.y, d00);
                        fma2(g0, G1.x, d01); fma2(g1, G1.y, d01);
                        fma2(k0, G0.x, d10); fma2(k1, G0.y, d10);
                        fma2(k0, G1.x, d11); fma2(k1, G1.y, d11);
                    }
                }
                {
                    float2 Fa = unpk(f0), Fb = unpk(f1);
                    float2 Ga = unpk(g0), Gb = unpk(g1);
                    float4 o;
                    o.x = fast_tanh(Fa.x) * fast_sig(Ga.x);
                    o.y = fast_tanh(Fa.y) * fast_sig(Ga.y);
                    o.z = fast_tanh(Fb.x) * fast_sig(Gb.x);
                    o.w = fast_tanh(Fb.y) * fast_sig(Gb.y);
                    *(float4*)&GT[u0*XS + cb] = o;
                }
                if (v1) {
                    float2 Fa = unpk(h0), Fb = unpk(h1);
                    float2 Ga = unpk(k0), Gb = unpk(k1);
                    float4 o;
                    o.x = fast_tanh(Fa.x) * fast_sig(Ga.x);
                    o.y = fast_tanh(Fa.y) * fast_sig(Ga.y);
                    o.z = fast_tanh(Fb.x) * fast_sig(Gb.x);
                    o.w = fast_tanh(Fb.y) * fast_sig(Gb.y);
                    *(float4*)&GT[u1*XS + cb] = o;
                }
            } else {
                const int rB = pg << 4;
                const int u0 = lane, u1 = lane + 32;
                const bool dual = (mode == 1);
                const bool v0 = (u0 < W);
                const bool v1 = dual && (u1 < W);
                const int uu0 = v0 ? u0 : 0;
                const int uu1 = v1 ? u1 : 0;
                u64 f0, f1, g0, g1;
                if (pg == 0) {
                    f0 = pack2(BS[32+cb], BS[32+cb+1]); f1 = pack2(BS[32+cb+2], BS[32+cb+3]);
                    g0 = pack2(BS[64+cb], BS[64+cb+1]); g1 = pack2(BS[64+cb+2], BS[64+cb+3]);
                } else { f0 = f1 = g0 = g1 = dup2(0.f); }
                // BUGFIX R13: pos1 accumulators carry bias via pg0 (zero on pg1)
                u64 h0, h1, k0, k1;
                if (dual) { h0 = f0; h1 = f1; k0 = g0; k1 = g1; }
                else      { h0 = h1 = k0 = k1 = dup2(0.f); }
                const float* q00 = &RB[uu0*XS + rB];
                const float* q01 = &RB[(uu0 + 1)*XS + rB];
                const float* q10 = &RB[uu1*XS + rB];
                const float* q11 = &RB[(uu1 + 1)*XS + rB];
                if (dual) {
                    #pragma unroll
                    for (int r = 0; r < 16; r += 4) {
                        float4 xa0 = *(const float4*)(q00 + r);
                        float4 xb0 = *(const float4*)(q01 + r);
                        float4 xa1 = *(const float4*)(q10 + r);
                        float4 xb1 = *(const float4*)(q11 + r);
                        #pragma unroll
                        for (int rr = 0; rr < 4; rr++) {
                            u64 d00 = dup2((&xa0.x)[rr]), d01 = dup2((&xb0.x)[rr]);
                            u64 d10 = dup2((&xa1.x)[rr]), d11 = dup2((&xb1.x)[rr]);
                            const float* wf = &WF[(2*(rB + r + rr))*XS + cb];
                            ulonglong2 F0 = *(const ulonglong2*)wf;
                            ulonglong2 F1 = *(const ulonglong2*)(wf + XS);
                            fma2(f0, F0.x, d00); fma2(f1, F0.y, d00);
                            fma2(f0, F1.x, d01); fma2(f1, F1.y, d01);
                            fma2(h0, F0.x, d10); fma2(h1, F0.y, d10);
                            fma2(h0, F1.x, d11); fma2(h1, F1.y, d11);
                            const float* wg = &WG[(2*(rB + r + rr))*XS + cb];
                            ulonglong2 G0 = *(const ulonglong2*)wg;
                            ulonglong2 G1 = *(const ulonglong2*)(wg + XS);
                            fma2(g0, G0.x, d00); fma2(g1, G0.y, d00);
                            fma2(g0, G1.x, d01); fma2(g1, G1.y, d01);
                            fma2(k0, G0.x, d10); fma2(k1, G0.y, d10);
                            fma2(k0, G1.x, d11); fma2(k1, G1.y, d11);
                        }
                    }
                } else {
                    #pragma unroll
                    for (int r = 0; r < 16; r += 4) {
                        float4 xa0 = *(const float4*)(q00 + r);
                        float4 xb0 = *(const float4*)(q01 + r);
                        #pragma unroll
                        for (int rr = 0; rr < 4; rr++) {
                            u64 d00 = dup2((&xa0.x)[rr]), d01 = dup2((&xb0.x)[rr]);
                            const float* wf = &WF[(2*(rB + r + rr))*XS + cb];
                            ulonglong2 F0 = *(const ulonglong2*)wf;
                            ulonglong2 F1 = *(const ulonglong2*)(wf + XS);
                            fma2(f0, F0.x, d00); fma2(f1, F0.y, d00);
                            fma2(f0, F1.x, d01); fma2(f1, F1.y, d01);
                            const float* wg = &WG[(2*(rB + r + rr))*XS + cb];
                            ulonglong2 G0 = *(const ulonglong2*)wg;
                            ulonglong2 G1 = *(const ulonglong2*)(wg + XS);
                            fma2(g0, G0.x, d00); fma2(g1, G0.y, d00);
                            fma2(g0, G1.x, d01); fma2(g1, G1.y, d01);
                        }
                    }
                }
                if (pg) {
                    { ulonglong2 t0; t0.x = f0; t0.y = f1; *(ulonglong2*)&PB[u0*XS + cb] = t0; }
                    { ulonglong2 t1; t1.x = g0; t1.y = g1; *(ulonglong2*)&PBG[u0*XS + cb] = t1; }
                    if (dual) {
                        { ulonglong2 t0; t0.x = h0; t0.y = h1; *(ulonglong2*)&PB[u1*XS + cb] = t0; }
                        { ulonglong2 t1; t1.x = k0; t1.y = k1; *(ulonglong2*)&PBG[u1*XS + cb] = t1; }
                    }
                }
                asm volatile("bar.sync 2, 512;" ::: "memory");
                if (!pg) {
                    if (v0) {
                        ulonglong2 pf = *(const ulonglong2*)&PB[u0*XS + cb];
                        ulonglong2 pgv = *(const ulonglong2*)&PBG[u0*XS + cb];
                        u64 F0v = add2(f0, pf.x), F1v = add2(f1, pf.y);
                        u64 G0v = add2(g0, pgv.x), G1v = add2(g1, pgv.y);
                        float2 Fa = unpk(F0v), Fb = unpk(F1v);
                        float2 Ga = unpk(G0v), Gb = unpk(G1v);
                        float4 o;
                        o.x = fast_tanh(Fa.x) * fast_sig(Ga.x);
                        o.y = fast_tanh(Fa.y) * fast_sig(Ga.y);
                        o.z = fast_tanh(Fb.x) * fast_sig(Gb.x);
                        o.w = fast_tanh(Fb.y) * fast_sig(Gb.y);
                        *(float4*)&GT[u0*XS + cb] = o;
                    }
                    if (v1) {
                        ulonglong2 pf = *(const ulonglong2*)&PB[u1*XS + cb];
                        ulonglong2 pgv = *(const ulonglong2*)&PBG[u1*XS + cb];
                        u64 F0v = add2(h0, pf.x), F1v = add2(h1, pf.y);
                        u64 G0v = add2(k0, pgv.x), G1v = add2(k1, pgv.y);
                        float2 Fa = unpk(F0v), Fb = unpk(F1v);
                        float2 Ga = unpk(G0v), Gb = unpk(G1v);
                        float4 o;
                        o.x = fast_tanh(Fa.x) * fast_sig(Ga.x);
                        o.y = fast_tanh(Fa.y) * fast_sig(Ga.y);
                        o.z = fast_tanh(Fb.x) * fast_sig(Gb.x);
                        o.w = fast_tanh(Fb.y) * fast_sig(Gb.y);
                        *(float4*)&GT[u1*XS + cb] = o;
                    }
                }
            }
        }
        __syncthreads();

        // ---- res 1x1 + residual -> X ----
        if (li < 15) {
            if (warp < 16) {
                if (mode == 0) {
                    const int u0 = lane + 32 * pg, u1 = u0 + 64;
                    const bool v1 = (u1 < W);
                    const int uu1 = v1 ? u1 : 0;
                    u64 a0 = pack2(BS[96+cb], BS[96+cb+1]);
                    u64 a1 = pack2(BS[96+cb+2], BS[96+cb+3]);
                    u64 b0 = a0, b1 = a1;
                    const float* p0 = &GT[u0*XS];
                    const float* p1 = &GT[uu1*XS];
                    #pragma unroll
                    for (int r = 0; r < 32; r += 4) {
                        float4 xa0 = *(const float4*)(p0 + r);
                        float4 xa1 = *(const float4*)(p1 + r);
                        #pragma unroll
                        for (int rr = 0; rr < 4; rr++) {
                            u64 d0 = dup2((&xa0.x)[rr]);
                            u64 d1 = dup2((&xa1.x)[rr]);
                            ulonglong2 Wv = *(const ulonglong2*)&WRs[(r + rr)*XS + cb];
                            fma2(a0, Wv.x, d0); fma2(a1, Wv.y, d0);
                            fma2(b0, Wv.x, d1); fma2(b1, Wv.y, d1);
                        }
                    }
                    {
                        ulonglong2 rv = *(const ulonglong2*)&RB[u0*XS + cb];
                        ulonglong2 t0; t0.x = add2(a0, rv.x); t0.y = add2(a1, rv.y);
                        *(ulonglong2*)&X[u0*XS + cb] = t0;
                    }
                    if (v1) {
                        ulonglong2 rv = *(const ulonglong2*)&RB[u1*XS + cb];
                        ulonglong2 t0; t0.x = add2(b0, rv.x); t0.y = add2(b1, rv.y);
                        *(ulonglong2*)&X[u1*XS + cb] = t0;
                    }
                } else {
                    const int rB = pg << 4;
                    const int u0 = lane, u1 = lane + 32;
                    const bool dual = (mode == 1);
                    const bool v0 = (u0 < W);
                    const bool v1 = dual && (u1 < W);
                    const int uu0 = v0 ? u0 : 0;
                    const int uu1 = v1 ? u1 : 0;
                    u64 a0, a1;
                    if (pg == 0) { a0 = pack2(BS[96+cb], BS[96+cb+1]); a1 = pack2(BS[96+cb+2], BS[96+cb+3]); }
                    else         { a0 = dup2(0.f); a1 = dup2(0.f); }
                    // BUGFIX R13: pos1 accumulator carries bias via pg0
                    u64 b0, b1;
                    if (dual) { b0 = a0; b1 = a1; }
                    else      { b0 = dup2(0.f); b1 = dup2(0.f); }
                    const float* q0 = &GT[uu0*XS + rB];
                    const float* q1 = &GT[uu1*XS + rB];
                    if (dual) {
                        #pragma unroll
                        for (int r = 0; r < 16; r += 4) {
                            float4 xa0 = *(const float4*)(q0 + r);
                            float4 xa1 = *(const float4*)(q1 + r);
                            #pragma unroll
                            for (int rr = 0; rr < 4; rr++) {
                                u64 d0 = dup2((&xa0.x)[rr]);
                                u64 d1 = dup2((&xa1.x)[rr]);
                                ulonglong2 Wv = *(const ulonglong2*)&WRs[(rB + r + rr)*XS + cb];
                                fma2(a0, Wv.x, d0); fma2(a1, Wv.y, d0);
                                fma2(b0, Wv.x, d1); fma2(b1, Wv.y, d1);
                            }
                        }
                    } else {
                        #pragma unroll
                        for (int r = 0; r < 16; r += 8) {
                            float4 xa0 = *(const float4*)(q0 + r);
                            float4 xb0 = *(const float4*)(q0 + r + 4);
                            #pragma unroll
                            for (int rr = 0; rr < 4; rr++) {
                                u64 d0 = dup2((&xa0.x)[rr]);
                                u64 d1 = dup2((&xb0.x)[rr]);
                                ulonglong2 W0 = *(const ulonglong2*)&WRs[(rB + r + rr)*XS + cb];
                                ulonglong2 W1 = *(const ulonglong2*)&WRs[(rB + r + rr + 4)*XS + cb];
                                fma2(a0, W0.x, d0); fma2(a1, W0.y, d0);
                                fma2(b0, W1.x, d1); fma2(b1, W1.y, d1);
                            }
                        }
                        a0 = add2(a0, b0); a1 = add2(a1, b1);
                    }
                    if (pg) {
                        { ulonglong2 t0; t0.x = a0; t0.y = a1; *(ulonglong2*)&PB[u0*XS + cb] = t0; }
                        if (dual) { ulonglong2 t0; t0.x = b0; t0.y = b1; *(ulonglong2*)&PB[u1*XS + cb] = t0; }
                    }
                    asm volatile("bar.sync 2, 512;" ::: "memory");
                    if (!pg) {
                        if (v0) {
                            ulonglong2 pp = *(const ulonglong2*)&PB[u0*XS + cb];
                            ulonglong2 rv = *(const ulonglong2*)&RB[u0*XS + cb];
                            ulonglong2 t0;
                            t0.x = add2(add2(a0, pp.x), rv.x);
                            t0.y = add2(add2(a1, pp.y), rv.y);
                            *(ulonglong2*)&X[u0*XS + cb] = t0;
                        }
                        if (v1) {
                            ulonglong2 pp = *(const ulonglong2*)&PB[u1*XS + cb];
                            ulonglong2 rv = *(const ulonglong2*)&RB[u1*XS + cb];
                            ulonglong2 t0;
                            t0.x = add2(add2(b0, pp.x), rv.x);
                            t0.y = add2(add2(b1, pp.y), rv.y);
                            *(ulonglong2*)&X[u1*XS + cb] = t0;
                        }
                    }
                }
            }
            __syncthreads();
        }
        cur++; if (cur == 3) cur = 0;
    }

    // ================= tail: skip/end/fc at t = T-1 only =================
    float* SV = RB;
    float* H1 = RB + 256;
    float* H2 = RB + 512;
    float* F1 = RB + 768;
    float* F2 = RB + 896;
    float* F3 = RB + 1024;

    const float* skw = skip_w + 15*256*32;
    const float* skb = skip_b + 15*256;
    float gv = GT[lane];
    #pragma unroll 2
    for (int o = warp; o < 256; o += 24) {
        float v = __ldg(&skw[o*32 + lane]) * gv;
        v = warp_sum(v);
        if (lane == 0) SV[o] = fmaxf(v + skb[o], 0.f);
    }
    __syncthreads();
    #pragma unroll 2
    for (int o = warp; o < 256; o += 24) {
        const float4* wp = (const float4*)(end1_w + o*256);
        const float4* sp = (const float4*)SV;
        float v = dot4(__ldg(wp + lane), sp[lane]) + dot4(__ldg(wp + lane + 32), sp[lane + 32]);
        v = warp_sum(v);
        if (lane == 0) H1[o] = fmaxf(v + end1_b[o], 0.f);
    }
    __syncthreads();
    #pragma unroll 2
    for (int o = warp; o < 256; o += 24) {
        const float4* wp = (const float4*)(end2_w + o*256);
        const float4* sp = (const float4*)H1;
        float v = dot4(__ldg(wp + lane), sp[lane]) + dot4(__ldg(wp + lane + 32), sp[lane + 32]);
        v = warp_sum(v);
        if (lane == 0) H2[o] = v + end2_b[o];
    }
    __syncthreads();
    #pragma unroll 2
    for (int o = warp; o < 128; o += 24) {
        const float4* wp = (const float4*)(fc1_w + o*256);
        const float4* sp = (const float4*)H2;
        float v = dot4(__ldg(wp + lane), sp[lane]) + dot4(__ldg(wp + lane + 32), sp[lane + 32]);
        v = warp_sum(v);
        if (lane == 0) F1[o] = fmaxf(v + fc1_b[o], 0.f);
    }
    __syncthreads();
    #pragma unroll 2
    for (int o = warp; o < 128; o += 24) {
        const float4* wp = (const float4*)(fc2_w + o*128);
        const float4* sp = (const float4*)F1;
        float v = dot4(__ldg(wp + lane), sp[lane]);
        v = warp_sum(v);
        if (lane == 0) F2[o] = fmaxf(v + fc2_b[o], 0.f);
    }
    __syncthreads();
    #pragma unroll 2
    for (int o = warp; o < 64; o += 24) {
        const float4* wp = (const float4*)(fc3_w + o*128);
        const float4* sp = (const float4*)F2;
        float v = dot4(__ldg(wp + lane), sp[lane]);
        v = warp_sum(v);
        if (lane == 0) F3[o] = fmaxf(v + fc3_b[o], 0.f);
    }
    __syncthreads();
    #pragma unroll 2
    for (int o = warp; o < 256; o += 24) {
        const float2* wp = (const float2*)(fc4_w + o*64);
        const float2* sp = (const float2*)F3;
        float2 wv = __ldg(wp + lane);
        float2 sv = sp[lane];
        float v = fmaf(wv.x, sv.x, wv.y * sv.y);
        v = warp_sum(v);
        if (lane == 0) out[b*256 + o] = v + fc4_b[o];
    }
}

extern "C" void kernel_launch(void* const* d_in, const int* in_sizes, int n_in,
                              void* d_out, int out_size)
{
    (void)in_sizes; (void)n_in; (void)out_size;
    const size_t smem_bytes = (size_t)SMEM_FLOATS * sizeof(float);
    cudaFuncSetAttribute(wavenet_kernel, cudaFuncAttributeMaxDynamicSharedMemorySize,
                         (int)smem_bytes);
    wavenet_kernel<<<16, NT, smem_bytes>>>(
        (const int*)  d_in[0],  (const float*)d_in[1],
        (const float*)d_in[2],  (const float*)d_in[3],
        (const float*)d_in[4],  (const float*)d_in[5],
        (const float*)d_in[6],  (const float*)d_in[7],
        (const float*)d_in[8],  (const float*)d_in[9],
        (const float*)d_in[10], (const float*)d_in[11],
        (const float*)d_in[12], (const float*)d_in[13],
        (const float*)d_in[14], (const float*)d_in[15],
        (const float*)d_in[16], (const float*)d_in[17],
        (const float*)d_in[18], (const float*)d_in[19],
        (const float*)d_in[20], (const float*)d_in[21],
        (const float*)d_in[22], (const float*)d_in[23],
        (const float*)d_in[24], (const float*)d_in[25],
        (float*)d_out);
}